// round 15
// baseline (speedup 1.0000x reference)
#include <cuda_runtime.h>
#include <cuda_fp16.h>
#include <math.h>
#include <stdint.h>

#define B_ 2
#define S_ 2048
#define D_ 1024
#define H_ 16
#define DH_ 64
#define F_ 4096
#define NTOK (B_ * S_)   // 4096

// ---------------- scratch (static device globals; no allocation) ----------------
__device__ float g_x1[(size_t)NTOK * D_];
__device__ __align__(16) __half g_qkvh[(size_t)NTOK * 3 * D_];
__device__ __align__(16) __half g_h[(size_t)NTOK * D_];
__device__ __align__(16) __half g_attn[(size_t)NTOK * D_];
__device__ __align__(16) __half g_ffn[(size_t)NTOK * F_];
__device__ __align__(16) __half g_wqkv[(size_t)3 * D_ * D_];
__device__ __align__(16) __half g_wout[(size_t)D_ * D_];
__device__ __align__(16) __half g_w1[(size_t)F_ * D_];
__device__ __align__(16) __half g_w2[(size_t)D_ * F_];

__device__ __forceinline__ uint32_t smem_u32(const void* p) {
    uint32_t a;
    asm("{ .reg .u64 t; cvta.to.shared.u64 t, %1; cvt.u32.u64 %0, t; }" : "=r"(a) : "l"(p));
    return a;
}

__device__ __forceinline__ uint32_t pack_h2(float x, float y) {
    __half2 h = __floats2half2_rn(x, y);
    return *(uint32_t*)&h;
}

// ---------------- fused weight convert: all 4 weights, one launch ----------------
#define NQ_WQKV (3 * D_ * D_ / 4)   // 786432
#define NQ_WOUT (D_ * D_ / 4)       // 262144
#define NQ_W1   (F_ * D_ / 4)       // 1048576
#define NQ_W2   (D_ * F_ / 4)       // 1048576
#define NQ_TOTAL (NQ_WQKV + NQ_WOUT + NQ_W1 + NQ_W2)  // 3145728

__global__ void __launch_bounds__(256) cvt_all_kernel(const float* __restrict__ s0,
                                                      const float* __restrict__ s1,
                                                      const float* __restrict__ s2,
                                                      const float* __restrict__ s3,
                                                      __half* __restrict__ d0,
                                                      __half* __restrict__ d1,
                                                      __half* __restrict__ d2,
                                                      __half* __restrict__ d3) {
    int i = blockIdx.x * 256 + threadIdx.x;
    const float* src;
    __half* dst;
    int off;
    if (i < NQ_WQKV) { src = s0; dst = d0; off = i; }
    else if (i < NQ_WQKV + NQ_WOUT) { src = s1; dst = d1; off = i - NQ_WQKV; }
    else if (i < NQ_WQKV + NQ_WOUT + NQ_W1) { src = s2; dst = d2; off = i - NQ_WQKV - NQ_WOUT; }
    else { src = s3; dst = d3; off = i - NQ_WQKV - NQ_WOUT - NQ_W1; }
    float4 f = ((const float4*)src)[off];
    ((uint2*)dst)[off] = make_uint2(pack_h2(f.x, f.y), pack_h2(f.z, f.w));
}

// ---------------- warp/block reduction helpers ----------------
__device__ __forceinline__ float warp_sum(float v) {
#pragma unroll
    for (int o = 16; o > 0; o >>= 1) v += __shfl_xor_sync(0xffffffffu, v, o);
    return v;
}

// ---------------- LayerNorm: fp32 in -> fp16 out ----------------
__global__ void __launch_bounds__(256) ln_kernel(const float* __restrict__ in,
                                                 __half* __restrict__ out,
                                                 const float* __restrict__ gamma,
                                                 const float* __restrict__ beta) {
    const int row = blockIdx.x;
    const float* x = in + (size_t)row * D_;
    const int tid = threadIdx.x;
    const int lane = tid & 31;
    const int wid = tid >> 5;

    float4 v = *(const float4*)(x + tid * 4);
    float s = v.x + v.y + v.z + v.w;
    __shared__ float red[8];
    s = warp_sum(s);
    if (lane == 0) red[wid] = s;
    __syncthreads();
    if (tid < 32) {
        float t = (lane < 8) ? red[lane] : 0.f;
        t = warp_sum(t);
        if (lane == 0) red[0] = t;
    }
    __syncthreads();
    const float mean = red[0] * (1.f / D_);
    __syncthreads();

    float q = (v.x - mean) * (v.x - mean) + (v.y - mean) * (v.y - mean) +
              (v.z - mean) * (v.z - mean) + (v.w - mean) * (v.w - mean);
    q = warp_sum(q);
    if (lane == 0) red[wid] = q;
    __syncthreads();
    if (tid < 32) {
        float t = (lane < 8) ? red[lane] : 0.f;
        t = warp_sum(t);
        if (lane == 0) red[0] = t;
    }
    __syncthreads();
    const float stdv = sqrtf(red[0] * (1.f / D_));
    const float inv = 1.f / (stdv + 1e-6f);

    float4 g = *(const float4*)(gamma + tid * 4);
    float4 b = *(const float4*)(beta + tid * 4);
    uint2 o;
    o.x = pack_h2(g.x * ((v.x - mean) * inv) + b.x, g.y * ((v.y - mean) * inv) + b.y);
    o.y = pack_h2(g.z * ((v.z - mean) * inv) + b.z, g.w * ((v.w - mean) * inv) + b.w);
    ((uint2*)out)[((size_t)row * D_ + tid * 4) >> 2] = o;
}

// ============================================================================
// fp16 mma.sync GEMM (fp32 accum), 3-stage cp.async pipeline, ONE sync/chunk.
// C[M,N] = A[M,K] * B[N,K]^T (+epilogue)
// EPI: 0 ->fp32, 1 +res->fp32, 2 +bias+GELU->fp16, 3 +bias+res->fp32, 4 ->fp16
// CTA 128x128, 8 warps (2m x 4n), warp 64x32, K-chunk 64, 2 CTAs/SM.
// Tile row: 64 fp16 = 128B data, 144B pitch (conflict-free ldmatrix).
// ============================================================================
#define ROWB 144
#define TILEB (128 * ROWB)           // 18432
#define OFF_B TILEB
#define STAGE_BYTES (2 * TILEB)      // 36864
#define GEMM_SMEM (3 * STAGE_BYTES)  // 110592 (x2 CTAs = 216 KB <= 228 KB)

#define LDSM4(r, addr) \
    asm volatile("ldmatrix.sync.aligned.m8n8.x4.shared.b16 {%0,%1,%2,%3}, [%4];" \
                 : "=r"((r)[0]), "=r"((r)[1]), "=r"((r)[2]), "=r"((r)[3]) : "r"(addr))
#define LDSM4T(r, addr) \
    asm volatile("ldmatrix.sync.aligned.m8n8.x4.trans.shared.b16 {%0,%1,%2,%3}, [%4];" \
                 : "=r"((r)[0]), "=r"((r)[1]), "=r"((r)[2]), "=r"((r)[3]) : "r"(addr))
#define MMA_F16(c, a, b) \
    asm volatile("mma.sync.aligned.m16n8k16.row.col.f32.f16.f16.f32 " \
                 "{%0,%1,%2,%3}, {%4,%5,%6,%7}, {%8,%9}, {%0,%1,%2,%3};" \
                 : "+f"((c)[0]), "+f"((c)[1]), "+f"((c)[2]), "+f"((c)[3]) \
                 : "r"((a)[0]), "r"((a)[1]), "r"((a)[2]), "r"((a)[3]), \
                   "r"((b)[0]), "r"((b)[1]))
#define CPASYNC(dst, src) \
    asm volatile("cp.async.ca.shared.global [%0], [%1], 16;" :: "r"(dst), "l"(src))
#define CPCOMMIT() asm volatile("cp.async.commit_group;")
#define CPWAIT0()  asm volatile("cp.async.wait_group 0;")
#define CPWAIT1()  asm volatile("cp.async.wait_group 1;")

__device__ __forceinline__ void copy_stage(uint32_t sdst,
                                           const __half* __restrict__ A,
                                           const __half* __restrict__ B,
                                           int K, int k0, int tid) {
#pragma unroll
    for (int t = 0; t < 4; t++) {
        int idx = tid + t * 256;          // 0..1023
        int r = idx >> 3, c = idx & 7;    // row, 16B chunk (8 fp16)
        uint32_t off = (uint32_t)r * ROWB + c * 16;
        size_t g = (size_t)r * K + k0 + c * 8;
        CPASYNC(sdst + off,         A + g);
        CPASYNC(sdst + off + OFF_B, B + g);
    }
}

template <int EPI>
__global__ void __launch_bounds__(256, 2) mma_gemm(int M, int N, int K,
                                                   const __half* __restrict__ A,
                                                   const __half* __restrict__ B,
                                                   float* __restrict__ C,
                                                   __half* __restrict__ Ch,
                                                   const float* __restrict__ bias,
                                                   const float* __restrict__ res) {
    extern __shared__ char smem[];
    const uint32_t sb = smem_u32(smem);
    const int tid = threadIdx.x;
    const int wid = tid >> 5;
    const int lane = tid & 31;
    const int warp_m = wid >> 2;
    const int warp_n = wid & 3;

    const __half* Ab = A + (size_t)(blockIdx.y * 128) * K;
    const __half* Bb = B + (size_t)(blockIdx.x * 128) * K;

    float acc[4][4][4];
#pragma unroll
    for (int i = 0; i < 4; i++)
#pragma unroll
        for (int j = 0; j < 4; j++)
#pragma unroll
            for (int u = 0; u < 4; u++) acc[i][j][u] = 0.f;

    const int nc = K >> 6;   // K / 64

    const int a_lrow = lane & 15;
    const int a_lbyte = (lane >> 4) * 16;
    const int bj = lane >> 3;
    const int b_lrow = (bj >> 1) * 8 + (lane & 7);
    const int b_lbyte = (bj & 1) * 16;

    // prologue: chunks 0,1 in flight
    copy_stage(sb, Ab, Bb, K, 0, tid);
    CPCOMMIT();
    copy_stage(sb + STAGE_BYTES, Ab, Bb, K, 64, tid);
    CPCOMMIT();

    for (int c = 0; c < nc; c++) {
        const uint32_t st = sb + (uint32_t)(c % 3) * STAGE_BYTES;
        if (c + 1 < nc) { CPWAIT1(); } else { CPWAIT0(); }
        __syncthreads();   // single barrier: chunk c ready AND stage (c+2)%3 free
        if (c + 2 < nc) {
            copy_stage(sb + (uint32_t)((c + 2) % 3) * STAGE_BYTES, Ab, Bb, K, (c + 2) << 6, tid);
            CPCOMMIT();
        }

#pragma unroll
        for (int ks = 0; ks < 4; ks++) {
            uint32_t af[4][4];
#pragma unroll
            for (int mf = 0; mf < 4; mf++) {
                const uint32_t row = warp_m * 64 + mf * 16 + a_lrow;
                LDSM4(af[mf], st + row * ROWB + ks * 32 + a_lbyte);
            }
            uint32_t bf[4][2];
#pragma unroll
            for (int nf2 = 0; nf2 < 2; nf2++) {
                const uint32_t row = warp_n * 32 + nf2 * 16 + b_lrow;
                uint32_t r[4];
                LDSM4(r, st + OFF_B + row * ROWB + ks * 32 + b_lbyte);
                bf[nf2 * 2][0] = r[0]; bf[nf2 * 2][1] = r[1];
                bf[nf2 * 2 + 1][0] = r[2]; bf[nf2 * 2 + 1][1] = r[3];
            }
#pragma unroll
            for (int mf = 0; mf < 4; mf++)
#pragma unroll
                for (int nf = 0; nf < 4; nf++)
                    MMA_F16(acc[mf][nf], af[mf], bf[nf]);
        }
    }

    const int rbase = blockIdx.y * 128 + warp_m * 64 + (lane >> 2);
    const int cbase = blockIdx.x * 128 + warp_n * 32 + (lane & 3) * 2;
#pragma unroll
    for (int mf = 0; mf < 4; mf++) {
#pragma unroll
        for (int h = 0; h < 2; h++) {
            const int row_g = rbase + mf * 16 + h * 8;
            const float* Rrow = (EPI == 1 || EPI == 3) ? res + (size_t)row_g * N : nullptr;
#pragma unroll
            for (int nf = 0; nf < 4; nf++) {
                const int col_g = cbase + nf * 8;
                float t0 = acc[mf][nf][2 * h];
                float t1 = acc[mf][nf][2 * h + 1];
                if (EPI == 2 || EPI == 3) { t0 += bias[col_g]; t1 += bias[col_g + 1]; }
                if (EPI == 2) {
                    t0 = 0.5f * t0 * (1.f + erff(t0 * 0.70710678118654752f));
                    t1 = 0.5f * t1 * (1.f + erff(t1 * 0.70710678118654752f));
                }
                if (EPI == 1 || EPI == 3) { t0 += Rrow[col_g]; t1 += Rrow[col_g + 1]; }
                if (EPI == 2 || EPI == 4) {
                    *(uint32_t*)(Ch + (size_t)row_g * N + col_g) = pack_h2(t0, t1);
                } else {
                    float2 p; p.x = t0; p.y = t1;
                    *(float2*)(C + (size_t)row_g * N + col_g) = p;
                }
            }
        }
    }
}

// ============================================================================
// MMA flash attention (fp16 inputs from g_qkvh, fp32 accum + softmax, causal).
// 128 threads = 4 warps, warp = 32 q-rows. Epilogue emits fp16.
// ============================================================================
#define APITCH 144
#define AT_Q 0
#define AT_K 18432
#define AT_V 27648
#define AT_SMEM 36864

__global__ void __launch_bounds__(128) attn_mma() {
    extern __shared__ char smem[];
    const uint32_t sb = smem_u32(smem);
    const int tid = threadIdx.x;
    const int lane = tid & 31;
    const int wid = tid >> 5;
    const int q0 = blockIdx.x * 128;
    const int hh = blockIdx.y;
    const int bb = blockIdx.z;

    // Q tile: 128 rows x 64 halves (8 x 16B chunks per row)
#pragma unroll
    for (int i = 0; i < 8; i++) {
        int idx = tid + i * 128;
        int r = idx >> 3, c = idx & 7;
        uint4 v = *(const uint4*)(g_qkvh + (size_t)(bb * S_ + q0 + r) * (3 * D_) + hh * DH_ + c * 8);
        *(uint4*)(smem + AT_Q + (uint32_t)r * APITCH + c * 16) = v;
    }

    float O[2][8][4];
#pragma unroll
    for (int a = 0; a < 2; a++)
#pragma unroll
        for (int b = 0; b < 8; b++)
#pragma unroll
            for (int u = 0; u < 4; u++) O[a][b][u] = 0.f;
    float mrow[2][2] = {{-INFINITY, -INFINITY}, {-INFINITY, -INFINITY}};
    float lrow[2][2] = {{0.f, 0.f}, {0.f, 0.f}};

    const int a_lrow = lane & 15;
    const int a_lbyte = (lane >> 4) * 16;
    const int bj = lane >> 3;
    const int b_lrow = (bj >> 1) * 8 + (lane & 7);
    const int b_lbyte = (bj & 1) * 16;
    const int v_key = (bj & 1) * 8 + (lane & 7);
    const int v_d = (bj >> 1) * 8;

    const int ntiles = blockIdx.x * 2 + 2;
    const int rowmax_warp = q0 + wid * 32 + 31;

    for (int t0 = 0; t0 < ntiles; t0++) {
        const int k0 = t0 * 64;
        __syncthreads();
#pragma unroll
        for (int i = 0; i < 4; i++) {
            int idx = tid + i * 128;
            int r = idx >> 3, c = idx & 7;
            const __half* kb = g_qkvh + (size_t)(bb * S_ + k0 + r) * (3 * D_) + D_ + hh * DH_ + c * 8;
            *(uint4*)(smem + AT_K + (uint32_t)r * APITCH + c * 16) = *(const uint4*)kb;
            *(uint4*)(smem + AT_V + (uint32_t)r * APITCH + c * 16) = *(const uint4*)(kb + D_);
        }
        __syncthreads();
        if (k0 > rowmax_warp) continue;

        float S[2][8][4] = {};
#pragma unroll
        for (int kf = 0; kf < 4; kf++) {
            uint32_t qf[2][4];
#pragma unroll
            for (int mf = 0; mf < 2; mf++) {
                LDSM4(qf[mf], sb + AT_Q + (uint32_t)(wid * 32 + mf * 16 + a_lrow) * APITCH + kf * 32 + a_lbyte);
            }
            uint32_t kfr[8][2];
#pragma unroll
            for (int p = 0; p < 4; p++) {
                uint32_t r4[4];
                LDSM4(r4, sb + AT_K + (uint32_t)(p * 16 + b_lrow) * APITCH + kf * 32 + b_lbyte);
                kfr[2 * p][0] = r4[0]; kfr[2 * p][1] = r4[1];
                kfr[2 * p + 1][0] = r4[2]; kfr[2 * p + 1][1] = r4[3];
            }
#pragma unroll
            for (int mf = 0; mf < 2; mf++)
#pragma unroll
                for (int nf = 0; nf < 8; nf++)
                    MMA_F16(S[mf][nf], qf[mf], kfr[nf]);
        }

#pragma unroll
        for (int mf = 0; mf < 2; mf++)
#pragma unroll
            for (int h = 0; h < 2; h++) {
                const int rowg = q0 + wid * 32 + mf * 16 + (lane >> 2) + h * 8;
                float tmax = -INFINITY;
#pragma unroll
                for (int nf = 0; nf < 8; nf++) {
                    const int colg = k0 + nf * 8 + (lane & 3) * 2;
                    float s0 = S[mf][nf][2 * h] * 0.125f;
                    float s1 = S[mf][nf][2 * h + 1] * 0.125f;
                    if (colg > rowg) s0 = -INFINITY;
                    if (colg + 1 > rowg) s1 = -INFINITY;
                    S[mf][nf][2 * h] = s0;
                    S[mf][nf][2 * h + 1] = s1;
                    tmax = fmaxf(tmax, fmaxf(s0, s1));
                }
                tmax = fmaxf(tmax, __shfl_xor_sync(0xffffffffu, tmax, 1));
                tmax = fmaxf(tmax, __shfl_xor_sync(0xffffffffu, tmax, 2));
                const float mn = fmaxf(mrow[mf][h], tmax);
                const float corr = __expf(mrow[mf][h] - mn);
                mrow[mf][h] = mn;
                float ps = 0.f;
#pragma unroll
                for (int nf = 0; nf < 8; nf++) {
                    float p0 = __expf(S[mf][nf][2 * h] - mn);
                    float p1 = __expf(S[mf][nf][2 * h + 1] - mn);
                    S[mf][nf][2 * h] = p0;
                    S[mf][nf][2 * h + 1] = p1;
                    ps += p0 + p1;
                }
                ps += __shfl_xor_sync(0xffffffffu, ps, 1);
                ps += __shfl_xor_sync(0xffffffffu, ps, 2);
                lrow[mf][h] = lrow[mf][h] * corr + ps;
#pragma unroll
                for (int nd = 0; nd < 8; nd++) {
                    O[mf][nd][2 * h] *= corr;
                    O[mf][nd][2 * h + 1] *= corr;
                }
            }

#pragma unroll
        for (int kf = 0; kf < 4; kf++) {
            uint32_t pf[2][4];
#pragma unroll
            for (int mf = 0; mf < 2; mf++) {
                pf[mf][0] = pack_h2(S[mf][2 * kf][0], S[mf][2 * kf][1]);
                pf[mf][1] = pack_h2(S[mf][2 * kf][2], S[mf][2 * kf][3]);
                pf[mf][2] = pack_h2(S[mf][2 * kf + 1][0], S[mf][2 * kf + 1][1]);
                pf[mf][3] = pack_h2(S[mf][2 * kf + 1][2], S[mf][2 * kf + 1][3]);
            }
            uint32_t vf[8][2];
#pragma unroll
            for (int db = 0; db < 4; db++) {
                uint32_t r4[4];
                LDSM4T(r4, sb + AT_V + (uint32_t)(kf * 16 + v_key) * APITCH + (db * 16 + v_d) * 2);
                vf[2 * db][0] = r4[0]; vf[2 * db][1] = r4[1];
                vf[2 * db + 1][0] = r4[2]; vf[2 * db + 1][1] = r4[3];
            }
#pragma unroll
            for (int mf = 0; mf < 2; mf++)
#pragma unroll
                for (int nd = 0; nd < 8; nd++)
                    MMA_F16(O[mf][nd], pf[mf], vf[nd]);
        }
    }

    // epilogue: O /= l -> fp16
#pragma unroll
    for (int mf = 0; mf < 2; mf++)
#pragma unroll
        for (int h = 0; h < 2; h++) {
            const float inv = 1.f / lrow[mf][h];
            const int rowg = q0 + wid * 32 + mf * 16 + (lane >> 2) + h * 8;
            const size_t rowoff = (size_t)(bb * S_ + rowg) * D_ + hh * DH_;
#pragma unroll
            for (int nd = 0; nd < 8; nd++) {
                const int col = nd * 8 + (lane & 3) * 2;
                *(uint32_t*)(g_attn + rowoff + col) =
                    pack_h2(O[mf][nd][2 * h] * inv, O[mf][nd][2 * h + 1] * inv);
            }
        }
}

// ---------------- launch ----------------
extern "C" void kernel_launch(void* const* d_in, const int* in_sizes, int n_in,
                              void* d_out, int out_size) {
    const float* x = (const float*)d_in[0];
    const float* Wqkv = (const float*)d_in[2];
    const float* Wout = (const float*)d_in[3];
    const float* W1 = (const float*)d_in[4];
    const float* b1 = (const float*)d_in[5];
    const float* W2 = (const float*)d_in[6];
    const float* b2 = (const float*)d_in[7];
    const float* gamma1 = (const float*)d_in[8];
    const float* beta1 = (const float*)d_in[9];
    const float* gamma2 = (const float*)d_in[10];
    const float* beta2 = (const float*)d_in[11];
    float* out = (float*)d_out;

    float* x1;
    __half *qkvh, *h, *attn, *ffn, *wq, *wo, *w1, *w2;
    cudaGetSymbolAddress((void**)&x1, g_x1);
    cudaGetSymbolAddress((void**)&qkvh, g_qkvh);
    cudaGetSymbolAddress((void**)&h, g_h);
    cudaGetSymbolAddress((void**)&attn, g_attn);
    cudaGetSymbolAddress((void**)&ffn, g_ffn);
    cudaGetSymbolAddress((void**)&wq, g_wqkv);
    cudaGetSymbolAddress((void**)&wo, g_wout);
    cudaGetSymbolAddress((void**)&w1, g_w1);
    cudaGetSymbolAddress((void**)&w2, g_w2);

    cudaFuncSetAttribute(mma_gemm<1>, cudaFuncAttributeMaxDynamicSharedMemorySize, GEMM_SMEM);
    cudaFuncSetAttribute(mma_gemm<2>, cudaFuncAttributeMaxDynamicSharedMemorySize, GEMM_SMEM);
    cudaFuncSetAttribute(mma_gemm<3>, cudaFuncAttributeMaxDynamicSharedMemorySize, GEMM_SMEM);
    cudaFuncSetAttribute(mma_gemm<4>, cudaFuncAttributeMaxDynamicSharedMemorySize, GEMM_SMEM);
    cudaFuncSetAttribute(attn_mma, cudaFuncAttributeMaxDynamicSharedMemorySize, AT_SMEM);

    // 0) fused weight convert fp32 -> fp16 (one launch)
    cvt_all_kernel<<<NQ_TOTAL / 256, 256>>>(Wqkv, Wout, W1, W2, wq, wo, w1, w2);

    // 1) LN1 -> fp16
    ln_kernel<<<NTOK, 256>>>(x, h, gamma1, beta1);
    // 2) QKV projection -> fp16 qkvh
    mma_gemm<4><<<dim3(3 * D_ / 128, NTOK / 128), 256, GEMM_SMEM>>>(
        NTOK, 3 * D_, D_, h, wq, nullptr, qkvh, nullptr, nullptr);
    // 3) causal flash attention -> fp16
    attn_mma<<<dim3(S_ / 128, H_, B_), 128, AT_SMEM>>>();
    // 4) output projection + residual -> fp32 x1
    mma_gemm<1><<<dim3(D_ / 128, NTOK / 128), 256, GEMM_SMEM>>>(
        NTOK, D_, D_, attn, wo, x1, nullptr, nullptr, x);
    // 5) LN2 -> fp16
    ln_kernel<<<NTOK, 256>>>(x1, h, gamma2, beta2);
    // 6) FFN1 + bias + exact GELU -> fp16
    mma_gemm<2><<<dim3(F_ / 128, NTOK / 128), 256, GEMM_SMEM>>>(
        NTOK, F_, D_, h, w1, nullptr, ffn, b1, nullptr);
    // 7) FFN2 + bias + residual -> out (fp32)
    mma_gemm<3><<<dim3(D_ / 128, NTOK / 128), 256, GEMM_SMEM>>>(
        NTOK, D_, F_, ffn, w2, out, nullptr, b2, x1);
}

// round 16
// speedup vs baseline: 1.1063x; 1.1063x over previous
#include <cuda_runtime.h>
#include <cuda_fp16.h>
#include <math.h>
#include <stdint.h>

#define B_ 2
#define S_ 2048
#define D_ 1024
#define H_ 16
#define DH_ 64
#define F_ 4096
#define NTOK (B_ * S_)   // 4096

// ---------------- scratch (static device globals; no allocation) ----------------
__device__ float g_x1[(size_t)NTOK * D_];
__device__ __align__(16) __half g_qkvh[(size_t)NTOK * 3 * D_];
__device__ __align__(16) __half g_h[(size_t)NTOK * D_];
__device__ __align__(16) __half g_attn[(size_t)NTOK * D_];
__device__ __align__(16) __half g_ffn[(size_t)NTOK * F_];
__device__ __align__(16) __half g_wqkv[(size_t)3 * D_ * D_];
__device__ __align__(16) __half g_wout[(size_t)D_ * D_];
__device__ __align__(16) __half g_w1[(size_t)F_ * D_];
__device__ __align__(16) __half g_w2[(size_t)D_ * F_];

__device__ __forceinline__ uint32_t smem_u32(const void* p) {
    uint32_t a;
    asm("{ .reg .u64 t; cvta.to.shared.u64 t, %1; cvt.u32.u64 %0, t; }" : "=r"(a) : "l"(p));
    return a;
}

__device__ __forceinline__ uint32_t pack_h2(float x, float y) {
    __half2 h = __floats2half2_rn(x, y);
    return *(uint32_t*)&h;
}

// ---------------- fused weight convert: all 4 weights, one launch ----------------
#define NQ_WQKV (3 * D_ * D_ / 4)   // 786432
#define NQ_WOUT (D_ * D_ / 4)       // 262144
#define NQ_W1   (F_ * D_ / 4)       // 1048576
#define NQ_W2   (D_ * F_ / 4)       // 1048576
#define NQ_TOTAL (NQ_WQKV + NQ_WOUT + NQ_W1 + NQ_W2)  // 3145728

__global__ void __launch_bounds__(256) cvt_all_kernel(const float* __restrict__ s0,
                                                      const float* __restrict__ s1,
                                                      const float* __restrict__ s2,
                                                      const float* __restrict__ s3,
                                                      __half* __restrict__ d0,
                                                      __half* __restrict__ d1,
                                                      __half* __restrict__ d2,
                                                      __half* __restrict__ d3) {
    int i = blockIdx.x * 256 + threadIdx.x;
    const float* src;
    __half* dst;
    int off;
    if (i < NQ_WQKV) { src = s0; dst = d0; off = i; }
    else if (i < NQ_WQKV + NQ_WOUT) { src = s1; dst = d1; off = i - NQ_WQKV; }
    else if (i < NQ_WQKV + NQ_WOUT + NQ_W1) { src = s2; dst = d2; off = i - NQ_WQKV - NQ_WOUT; }
    else { src = s3; dst = d3; off = i - NQ_WQKV - NQ_WOUT - NQ_W1; }
    float4 f = ((const float4*)src)[off];
    ((uint2*)dst)[off] = make_uint2(pack_h2(f.x, f.y), pack_h2(f.z, f.w));
}

// ---------------- warp/block reduction helpers ----------------
__device__ __forceinline__ float warp_sum(float v) {
#pragma unroll
    for (int o = 16; o > 0; o >>= 1) v += __shfl_xor_sync(0xffffffffu, v, o);
    return v;
}

// ---------------- LayerNorm: fp32 in -> fp16 out ----------------
__global__ void __launch_bounds__(256) ln_kernel(const float* __restrict__ in,
                                                 __half* __restrict__ out,
                                                 const float* __restrict__ gamma,
                                                 const float* __restrict__ beta) {
    const int row = blockIdx.x;
    const float* x = in + (size_t)row * D_;
    const int tid = threadIdx.x;
    const int lane = tid & 31;
    const int wid = tid >> 5;

    float4 v = *(const float4*)(x + tid * 4);
    float s = v.x + v.y + v.z + v.w;
    __shared__ float red[8];
    s = warp_sum(s);
    if (lane == 0) red[wid] = s;
    __syncthreads();
    if (tid < 32) {
        float t = (lane < 8) ? red[lane] : 0.f;
        t = warp_sum(t);
        if (lane == 0) red[0] = t;
    }
    __syncthreads();
    const float mean = red[0] * (1.f / D_);
    __syncthreads();

    float q = (v.x - mean) * (v.x - mean) + (v.y - mean) * (v.y - mean) +
              (v.z - mean) * (v.z - mean) + (v.w - mean) * (v.w - mean);
    q = warp_sum(q);
    if (lane == 0) red[wid] = q;
    __syncthreads();
    if (tid < 32) {
        float t = (lane < 8) ? red[lane] : 0.f;
        t = warp_sum(t);
        if (lane == 0) red[0] = t;
    }
    __syncthreads();
    const float stdv = sqrtf(red[0] * (1.f / D_));
    const float inv = 1.f / (stdv + 1e-6f);

    float4 g = *(const float4*)(gamma + tid * 4);
    float4 b = *(const float4*)(beta + tid * 4);
    uint2 o;
    o.x = pack_h2(g.x * ((v.x - mean) * inv) + b.x, g.y * ((v.y - mean) * inv) + b.y);
    o.y = pack_h2(g.z * ((v.z - mean) * inv) + b.z, g.w * ((v.w - mean) * inv) + b.w);
    ((uint2*)out)[((size_t)row * D_ + tid * 4) >> 2] = o;
}

// ============================================================================
// fp16 mma.sync GEMM (fp32 accum), cp.async double-buffered, 2 CTAs/SM.
// (reverted to the measured-best R13 configuration)
// C[M,N] = A[M,K] * B[N,K]^T (+epilogue)
// EPI: 0 ->fp32, 1 +res->fp32, 2 +bias+GELU->fp16, 3 +bias+res->fp32, 4 ->fp16
// CTA 128x128, 8 warps (2m x 4n), warp 64x32, K-chunk 64.
// Tile row: 64 fp16 = 128B data, 144B pitch (conflict-free ldmatrix).
// ============================================================================
#define ROWB 144
#define TILEB (128 * ROWB)        // 18432
#define OFF_B TILEB
#define STAGE_BYTES (2 * TILEB)   // 36864
#define GEMM_SMEM (2 * STAGE_BYTES)  // 73728

#define LDSM4(r, addr) \
    asm volatile("ldmatrix.sync.aligned.m8n8.x4.shared.b16 {%0,%1,%2,%3}, [%4];" \
                 : "=r"((r)[0]), "=r"((r)[1]), "=r"((r)[2]), "=r"((r)[3]) : "r"(addr))
#define LDSM4T(r, addr) \
    asm volatile("ldmatrix.sync.aligned.m8n8.x4.trans.shared.b16 {%0,%1,%2,%3}, [%4];" \
                 : "=r"((r)[0]), "=r"((r)[1]), "=r"((r)[2]), "=r"((r)[3]) : "r"(addr))
#define MMA_F16(c, a, b) \
    asm volatile("mma.sync.aligned.m16n8k16.row.col.f32.f16.f16.f32 " \
                 "{%0,%1,%2,%3}, {%4,%5,%6,%7}, {%8,%9}, {%0,%1,%2,%3};" \
                 : "+f"((c)[0]), "+f"((c)[1]), "+f"((c)[2]), "+f"((c)[3]) \
                 : "r"((a)[0]), "r"((a)[1]), "r"((a)[2]), "r"((a)[3]), \
                   "r"((b)[0]), "r"((b)[1]))
#define CPASYNC(dst, src) \
    asm volatile("cp.async.ca.shared.global [%0], [%1], 16;" :: "r"(dst), "l"(src))
#define CPCOMMIT() asm volatile("cp.async.commit_group;")
#define CPWAIT0()  asm volatile("cp.async.wait_group 0;")
#define CPWAIT1()  asm volatile("cp.async.wait_group 1;")

__device__ __forceinline__ void copy_stage(uint32_t sdst,
                                           const __half* __restrict__ A,
                                           const __half* __restrict__ B,
                                           int K, int k0, int tid) {
#pragma unroll
    for (int t = 0; t < 4; t++) {
        int idx = tid + t * 256;          // 0..1023
        int r = idx >> 3, c = idx & 7;    // row, 16B chunk (8 fp16)
        uint32_t off = (uint32_t)r * ROWB + c * 16;
        size_t g = (size_t)r * K + k0 + c * 8;
        CPASYNC(sdst + off,         A + g);
        CPASYNC(sdst + off + OFF_B, B + g);
    }
}

template <int EPI>
__global__ void __launch_bounds__(256, 2) mma_gemm(int M, int N, int K,
                                                   const __half* __restrict__ A,
                                                   const __half* __restrict__ B,
                                                   float* __restrict__ C,
                                                   __half* __restrict__ Ch,
                                                   const float* __restrict__ bias,
                                                   const float* __restrict__ res) {
    extern __shared__ char smem[];
    const uint32_t sb = smem_u32(smem);
    const int tid = threadIdx.x;
    const int wid = tid >> 5;
    const int lane = tid & 31;
    const int warp_m = wid >> 2;
    const int warp_n = wid & 3;

    const __half* Ab = A + (size_t)(blockIdx.y * 128) * K;
    const __half* Bb = B + (size_t)(blockIdx.x * 128) * K;

    float acc[4][4][4];
#pragma unroll
    for (int i = 0; i < 4; i++)
#pragma unroll
        for (int j = 0; j < 4; j++)
#pragma unroll
            for (int u = 0; u < 4; u++) acc[i][j][u] = 0.f;

    const int nc = K >> 6;   // K / 64

    const int a_lrow = lane & 15;
    const int a_lbyte = (lane >> 4) * 16;
    const int bj = lane >> 3;
    const int b_lrow = (bj >> 1) * 8 + (lane & 7);
    const int b_lbyte = (bj & 1) * 16;

    copy_stage(sb, Ab, Bb, K, 0, tid);
    CPCOMMIT();

    for (int c = 0; c < nc; c++) {
        const int buf = c & 1;
        const uint32_t st = sb + buf * STAGE_BYTES;

        if (c + 1 < nc) {
            copy_stage(sb + (buf ^ 1) * STAGE_BYTES, Ab, Bb, K, (c + 1) << 6, tid);
            CPCOMMIT();
            CPWAIT1();
        } else {
            CPWAIT0();
        }
        __syncthreads();

#pragma unroll
        for (int ks = 0; ks < 4; ks++) {
            uint32_t af[4][4];
#pragma unroll
            for (int mf = 0; mf < 4; mf++) {
                const uint32_t row = warp_m * 64 + mf * 16 + a_lrow;
                LDSM4(af[mf], st + row * ROWB + ks * 32 + a_lbyte);
            }
            uint32_t bf[4][2];
#pragma unroll
            for (int nf2 = 0; nf2 < 2; nf2++) {
                const uint32_t row = warp_n * 32 + nf2 * 16 + b_lrow;
                uint32_t r[4];
                LDSM4(r, st + OFF_B + row * ROWB + ks * 32 + b_lbyte);
                bf[nf2 * 2][0] = r[0]; bf[nf2 * 2][1] = r[1];
                bf[nf2 * 2 + 1][0] = r[2]; bf[nf2 * 2 + 1][1] = r[3];
            }
#pragma unroll
            for (int mf = 0; mf < 4; mf++)
#pragma unroll
                for (int nf = 0; nf < 4; nf++)
                    MMA_F16(acc[mf][nf], af[mf], bf[nf]);
        }
        __syncthreads();
    }

    const int rbase = blockIdx.y * 128 + warp_m * 64 + (lane >> 2);
    const int cbase = blockIdx.x * 128 + warp_n * 32 + (lane & 3) * 2;
#pragma unroll
    for (int mf = 0; mf < 4; mf++) {
#pragma unroll
        for (int h = 0; h < 2; h++) {
            const int row_g = rbase + mf * 16 + h * 8;
            const float* Rrow = (EPI == 1 || EPI == 3) ? res + (size_t)row_g * N : nullptr;
#pragma unroll
            for (int nf = 0; nf < 4; nf++) {
                const int col_g = cbase + nf * 8;
                float t0 = acc[mf][nf][2 * h];
                float t1 = acc[mf][nf][2 * h + 1];
                if (EPI == 2 || EPI == 3) { t0 += bias[col_g]; t1 += bias[col_g + 1]; }
                if (EPI == 2) {
                    t0 = 0.5f * t0 * (1.f + erff(t0 * 0.70710678118654752f));
                    t1 = 0.5f * t1 * (1.f + erff(t1 * 0.70710678118654752f));
                }
                if (EPI == 1 || EPI == 3) { t0 += Rrow[col_g]; t1 += Rrow[col_g + 1]; }
                if (EPI == 2 || EPI == 4) {
                    *(uint32_t*)(Ch + (size_t)row_g * N + col_g) = pack_h2(t0, t1);
                } else {
                    float2 p; p.x = t0; p.y = t1;
                    *(float2*)(C + (size_t)row_g * N + col_g) = p;
                }
            }
        }
    }
}

// ============================================================================
// MMA flash attention (fp16, fp32 accum + softmax, causal).
// Longest-job-first: q-block = gridDim.x-1-blockIdx.x so heavy CTAs launch first.
// 128 threads = 4 warps, warp = 32 q-rows. Epilogue emits fp16.
// ============================================================================
#define APITCH 144
#define AT_Q 0
#define AT_K 18432
#define AT_V 27648
#define AT_SMEM 36864

__global__ void __launch_bounds__(128) attn_mma() {
    extern __shared__ char smem[];
    const uint32_t sb = smem_u32(smem);
    const int tid = threadIdx.x;
    const int lane = tid & 31;
    const int wid = tid >> 5;
    const int qblk = gridDim.x - 1 - blockIdx.x;   // heavy blocks first
    const int q0 = qblk * 128;
    const int hh = blockIdx.y;
    const int bb = blockIdx.z;

    // Q tile: 128 rows x 64 halves (8 x 16B chunks per row)
#pragma unroll
    for (int i = 0; i < 8; i++) {
        int idx = tid + i * 128;
        int r = idx >> 3, c = idx & 7;
        uint4 v = *(const uint4*)(g_qkvh + (size_t)(bb * S_ + q0 + r) * (3 * D_) + hh * DH_ + c * 8);
        *(uint4*)(smem + AT_Q + (uint32_t)r * APITCH + c * 16) = v;
    }

    float O[2][8][4];
#pragma unroll
    for (int a = 0; a < 2; a++)
#pragma unroll
        for (int b = 0; b < 8; b++)
#pragma unroll
            for (int u = 0; u < 4; u++) O[a][b][u] = 0.f;
    float mrow[2][2] = {{-INFINITY, -INFINITY}, {-INFINITY, -INFINITY}};
    float lrow[2][2] = {{0.f, 0.f}, {0.f, 0.f}};

    const int a_lrow = lane & 15;
    const int a_lbyte = (lane >> 4) * 16;
    const int bj = lane >> 3;
    const int b_lrow = (bj >> 1) * 8 + (lane & 7);
    const int b_lbyte = (bj & 1) * 16;
    const int v_key = (bj & 1) * 8 + (lane & 7);
    const int v_d = (bj >> 1) * 8;

    const int ntiles = qblk * 2 + 2;
    const int rowmax_warp = q0 + wid * 32 + 31;

    for (int t0 = 0; t0 < ntiles; t0++) {
        const int k0 = t0 * 64;
        __syncthreads();
#pragma unroll
        for (int i = 0; i < 4; i++) {
            int idx = tid + i * 128;
            int r = idx >> 3, c = idx & 7;
            const __half* kb = g_qkvh + (size_t)(bb * S_ + k0 + r) * (3 * D_) + D_ + hh * DH_ + c * 8;
            *(uint4*)(smem + AT_K + (uint32_t)r * APITCH + c * 16) = *(const uint4*)kb;
            *(uint4*)(smem + AT_V + (uint32_t)r * APITCH + c * 16) = *(const uint4*)(kb + D_);
        }
        __syncthreads();
        if (k0 > rowmax_warp) continue;

        float S[2][8][4] = {};
#pragma unroll
        for (int kf = 0; kf < 4; kf++) {
            uint32_t qf[2][4];
#pragma unroll
            for (int mf = 0; mf < 2; mf++) {
                LDSM4(qf[mf], sb + AT_Q + (uint32_t)(wid * 32 + mf * 16 + a_lrow) * APITCH + kf * 32 + a_lbyte);
            }
            uint32_t kfr[8][2];
#pragma unroll
            for (int p = 0; p < 4; p++) {
                uint32_t r4[4];
                LDSM4(r4, sb + AT_K + (uint32_t)(p * 16 + b_lrow) * APITCH + kf * 32 + b_lbyte);
                kfr[2 * p][0] = r4[0]; kfr[2 * p][1] = r4[1];
                kfr[2 * p + 1][0] = r4[2]; kfr[2 * p + 1][1] = r4[3];
            }
#pragma unroll
            for (int mf = 0; mf < 2; mf++)
#pragma unroll
                for (int nf = 0; nf < 8; nf++)
                    MMA_F16(S[mf][nf], qf[mf], kfr[nf]);
        }

#pragma unroll
        for (int mf = 0; mf < 2; mf++)
#pragma unroll
            for (int h = 0; h < 2; h++) {
                const int rowg = q0 + wid * 32 + mf * 16 + (lane >> 2) + h * 8;
                float tmax = -INFINITY;
#pragma unroll
                for (int nf = 0; nf < 8; nf++) {
                    const int colg = k0 + nf * 8 + (lane & 3) * 2;
                    float s0 = S[mf][nf][2 * h] * 0.125f;
                    float s1 = S[mf][nf][2 * h + 1] * 0.125f;
                    if (colg > rowg) s0 = -INFINITY;
                    if (colg + 1 > rowg) s1 = -INFINITY;
                    S[mf][nf][2 * h] = s0;
                    S[mf][nf][2 * h + 1] = s1;
                    tmax = fmaxf(tmax, fmaxf(s0, s1));
                }
                tmax = fmaxf(tmax, __shfl_xor_sync(0xffffffffu, tmax, 1));
                tmax = fmaxf(tmax, __shfl_xor_sync(0xffffffffu, tmax, 2));
                const float mn = fmaxf(mrow[mf][h], tmax);
                const float corr = __expf(mrow[mf][h] - mn);
                mrow[mf][h] = mn;
                float ps = 0.f;
#pragma unroll
                for (int nf = 0; nf < 8; nf++) {
                    float p0 = __expf(S[mf][nf][2 * h] - mn);
                    float p1 = __expf(S[mf][nf][2 * h + 1] - mn);
                    S[mf][nf][2 * h] = p0;
                    S[mf][nf][2 * h + 1] = p1;
                    ps += p0 + p1;
                }
                ps += __shfl_xor_sync(0xffffffffu, ps, 1);
                ps += __shfl_xor_sync(0xffffffffu, ps, 2);
                lrow[mf][h] = lrow[mf][h] * corr + ps;
#pragma unroll
                for (int nd = 0; nd < 8; nd++) {
                    O[mf][nd][2 * h] *= corr;
                    O[mf][nd][2 * h + 1] *= corr;
                }
            }

#pragma unroll
        for (int kf = 0; kf < 4; kf++) {
            uint32_t pf[2][4];
#pragma unroll
            for (int mf = 0; mf < 2; mf++) {
                pf[mf][0] = pack_h2(S[mf][2 * kf][0], S[mf][2 * kf][1]);
                pf[mf][1] = pack_h2(S[mf][2 * kf][2], S[mf][2 * kf][3]);
                pf[mf][2] = pack_h2(S[mf][2 * kf + 1][0], S[mf][2 * kf + 1][1]);
                pf[mf][3] = pack_h2(S[mf][2 * kf + 1][2], S[mf][2 * kf + 1][3]);
            }
            uint32_t vf[8][2];
#pragma unroll
            for (int db = 0; db < 4; db++) {
                uint32_t r4[4];
                LDSM4T(r4, sb + AT_V + (uint32_t)(kf * 16 + v_key) * APITCH + (db * 16 + v_d) * 2);
                vf[2 * db][0] = r4[0]; vf[2 * db][1] = r4[1];
                vf[2 * db + 1][0] = r4[2]; vf[2 * db + 1][1] = r4[3];
            }
#pragma unroll
            for (int mf = 0; mf < 2; mf++)
#pragma unroll
                for (int nd = 0; nd < 8; nd++)
                    MMA_F16(O[mf][nd], pf[mf], vf[nd]);
        }
    }

    // epilogue: O /= l -> fp16
#pragma unroll
    for (int mf = 0; mf < 2; mf++)
#pragma unroll
        for (int h = 0; h < 2; h++) {
            const float inv = 1.f / lrow[mf][h];
            const int rowg = q0 + wid * 32 + mf * 16 + (lane >> 2) + h * 8;
            const size_t rowoff = (size_t)(bb * S_ + rowg) * D_ + hh * DH_;
#pragma unroll
            for (int nd = 0; nd < 8; nd++) {
                const int col = nd * 8 + (lane & 3) * 2;
                *(uint32_t*)(g_attn + rowoff + col) =
                    pack_h2(O[mf][nd][2 * h] * inv, O[mf][nd][2 * h + 1] * inv);
            }
        }
}

// ---------------- launch ----------------
extern "C" void kernel_launch(void* const* d_in, const int* in_sizes, int n_in,
                              void* d_out, int out_size) {
    const float* x = (const float*)d_in[0];
    const float* Wqkv = (const float*)d_in[2];
    const float* Wout = (const float*)d_in[3];
    const float* W1 = (const float*)d_in[4];
    const float* b1 = (const float*)d_in[5];
    const float* W2 = (const float*)d_in[6];
    const float* b2 = (const float*)d_in[7];
    const float* gamma1 = (const float*)d_in[8];
    const float* beta1 = (const float*)d_in[9];
    const float* gamma2 = (const float*)d_in[10];
    const float* beta2 = (const float*)d_in[11];
    float* out = (float*)d_out;

    float* x1;
    __half *qkvh, *h, *attn, *ffn, *wq, *wo, *w1, *w2;
    cudaGetSymbolAddress((void**)&x1, g_x1);
    cudaGetSymbolAddress((void**)&qkvh, g_qkvh);
    cudaGetSymbolAddress((void**)&h, g_h);
    cudaGetSymbolAddress((void**)&attn, g_attn);
    cudaGetSymbolAddress((void**)&ffn, g_ffn);
    cudaGetSymbolAddress((void**)&wq, g_wqkv);
    cudaGetSymbolAddress((void**)&wo, g_wout);
    cudaGetSymbolAddress((void**)&w1, g_w1);
    cudaGetSymbolAddress((void**)&w2, g_w2);

    cudaFuncSetAttribute(mma_gemm<1>, cudaFuncAttributeMaxDynamicSharedMemorySize, GEMM_SMEM);
    cudaFuncSetAttribute(mma_gemm<2>, cudaFuncAttributeMaxDynamicSharedMemorySize, GEMM_SMEM);
    cudaFuncSetAttribute(mma_gemm<3>, cudaFuncAttributeMaxDynamicSharedMemorySize, GEMM_SMEM);
    cudaFuncSetAttribute(mma_gemm<4>, cudaFuncAttributeMaxDynamicSharedMemorySize, GEMM_SMEM);
    cudaFuncSetAttribute(attn_mma, cudaFuncAttributeMaxDynamicSharedMemorySize, AT_SMEM);

    // 0) fused weight convert fp32 -> fp16 (one launch)
    cvt_all_kernel<<<NQ_TOTAL / 256, 256>>>(Wqkv, Wout, W1, W2, wq, wo, w1, w2);

    // 1) LN1 -> fp16
    ln_kernel<<<NTOK, 256>>>(x, h, gamma1, beta1);
    // 2) QKV projection -> fp16 qkvh
    mma_gemm<4><<<dim3(3 * D_ / 128, NTOK / 128), 256, GEMM_SMEM>>>(
        NTOK, 3 * D_, D_, h, wq, nullptr, qkvh, nullptr, nullptr);
    // 3) causal flash attention -> fp16 (longest-job-first ordering)
    attn_mma<<<dim3(S_ / 128, H_, B_), 128, AT_SMEM>>>();
    // 4) output projection + residual -> fp32 x1
    mma_gemm<1><<<dim3(D_ / 128, NTOK / 128), 256, GEMM_SMEM>>>(
        NTOK, D_, D_, attn, wo, x1, nullptr, nullptr, x);
    // 5) LN2 -> fp16
    ln_kernel<<<NTOK, 256>>>(x1, h, gamma2, beta2);
    // 6) FFN1 + bias + exact GELU -> fp16
    mma_gemm<2><<<dim3(F_ / 128, NTOK / 128), 256, GEMM_SMEM>>>(
        NTOK, F_, D_, h, w1, nullptr, ffn, b1, nullptr);
    // 7) FFN2 + bias + residual -> out (fp32)
    mma_gemm<3><<<dim3(D_ / 128, NTOK / 128), 256, GEMM_SMEM>>>(
        NTOK, D_, F_, ffn, w2, out, nullptr, b2, x1);
}